// round 9
// baseline (speedup 1.0000x reference)
#include <cuda_runtime.h>
#include <math.h>

#define NN 50000
#define EE 800000
#define F 32
#define H 64
#define NINVC 128
#define GMAX 2048
#define EPSF 1e-6f
#define TILE 128          // edges per block tile
#define EPW 16            // edges per warp in GEMM2

// ---------------- scratch (device globals; no allocation) ----------------
__device__ float4 d_sv[NN * F];    // packed node state {s, vx, vy, vz}
__device__ float4 d_acc[NN * F];   // packed accumulator {as, avx, avy, avz}
__device__ float d_cnt[NN];
__device__ float d_xgsum[GMAX * NINVC];
__device__ float d_gcnt[GMAX];
__device__ float d_xg[GMAX * NINVC];
__device__ float d_z1[GMAX * NINVC];
__device__ float d_m1[NINVC];
__device__ float d_r1[NINVC];
__device__ float d_m2[NINVC];
__device__ float d_r2[NINVC];

__device__ __forceinline__ float elu1(float x) { return x > 0.f ? x : expm1f(x); }

__device__ __forceinline__ void red_add_v4(float4* addr, float a, float b, float c, float d) {
    asm volatile("red.global.add.v4.f32 [%0], {%1, %2, %3, %4};"
                 :: "l"(addr), "f"(a), "f"(b), "f"(c), "f"(d) : "memory");
}

#define FMA2(acc, a, b) \
    asm("fma.rn.f32x2 %0, %1, %2, %0;" : "+l"(acc) : "l"(a), "l"(b))

#define PACK2(out, v) \
    asm("mov.b64 %0, {%1, %1};" : "=l"(out) : "r"(__float_as_uint(v)))

// shared memory layout (float offsets)
#define OF_W1   0        // 320
#define OF_B1   320      // 64
#define OF_B2   384      // 96
#define OF_W2T  480      // 6144  : [k/4][out][4] tiled
#define OF_EIN  6624     // 640   : [e][5]
#define OF_H    7264     // 8192  : h1T [k][e]
#define OF_U    15456    // 512   : float4 per edge {ux,uy,uz,-}
#define OF_SD   15968    // 256   : int2 per edge {src,dst}
#define SMEM_FLOATS 16224
#define SMEM_BYTES (SMEM_FLOATS * 4)

// ---------------- zero accumulators ----------------
__global__ void zero_kernel() {
    int stride = gridDim.x * blockDim.x;
    float4 z4 = make_float4(0.f, 0.f, 0.f, 0.f);
    for (int i = blockIdx.x * blockDim.x + threadIdx.x; i < NN * F; i += stride) {
        d_acc[i] = z4;
        if (i < NN) d_cnt[i] = 0.f;
        if (i < GMAX * NINVC) d_xgsum[i] = 0.f;
        if (i < GMAX) d_gcnt[i] = 0.f;
    }
}

// ---------------- embedding ----------------
__global__ void embed_kernel(const float* __restrict__ x, const float* __restrict__ pos,
                             const float* __restrict__ Wes, const float* __restrict__ bes,
                             const float* __restrict__ Wev, int Nn) {
    int idx = blockIdx.x * blockDim.x + threadIdx.x;
    if (idx >= Nn * F) return;
    int n = idx / F, f = idx & (F - 1);
    float xs[5];
#pragma unroll
    for (int i = 0; i < 5; i++) xs[i] = x[n * 5 + i];
    float as = bes[f], av = 0.f;
#pragma unroll
    for (int i = 0; i < 5; i++) { as += xs[i] * Wes[i * F + f]; av += xs[i] * Wev[i * F + f]; }
    float px = pos[n * 3], py = pos[n * 3 + 1], pz = pos[n * 3 + 2];
    d_sv[idx] = make_float4(as, av * px, av * py, av * pz);
}

// ---------------- in-degree over dst ----------------
__global__ void degree_kernel(const int* __restrict__ ei, int E) {
    int e = blockIdx.x * blockDim.x + threadIdx.x;
    if (e < E) atomicAdd(&d_cnt[ei[E + e]], 1.f);
}

// ---------------- fused edge MLP + message + scatter (per layer) ----------------
// TILE=128 edges/block; warp owns 16 edges; lane = feature f; f32x2 FMAs.
__global__ void __launch_bounds__(256) msg_kernel(
    const float* __restrict__ pos, const int* __restrict__ ei,
    const float* __restrict__ ea,
    const float* __restrict__ W1, const float* __restrict__ b1,
    const float* __restrict__ W2, const float* __restrict__ b2, int E) {
    extern __shared__ float smem[];
    float* sW1  = smem + OF_W1;
    float* sb1  = smem + OF_B1;
    float* sb2  = smem + OF_B2;
    float* sW2T = smem + OF_W2T;
    float* sEIn = smem + OF_EIN;
    float* h1T  = smem + OF_H;
    float4* sU4 = (float4*)(smem + OF_U);
    int2*  sSD  = (int2*)(smem + OF_SD);

    int tid = threadIdx.x;
    for (int i = tid; i < 5 * H; i += 256) sW1[i] = W1[i];
    if (tid < H) sb1[tid] = b1[tid];
    if (tid < 96) sb2[tid] = b2[tid];
    // W2 tiled: sW2T[k4*384 + o*4 + kk] = W2[(k4*4+kk)*96 + o]
    for (int i = tid; i < H * 96; i += 256) {
        int k4 = i / 384, r = i % 384, o = r >> 2, kk = r & 3;
        sW2T[i] = W2[(k4 * 4 + kk) * 96 + o];
    }

    int w = tid >> 5;        // warp 0..7
    int f = tid & 31;        // lane = feature
    int eBase = w * EPW;     // warp owns 16 edges

    int ntiles = (E + TILE - 1) / TILE;
    for (int t = blockIdx.x; t < ntiles; t += gridDim.x) {
        int e0 = t * TILE;
        __syncthreads();  // previous tile fully consumed; weights visible
        if (tid < TILE) {
            int e = e0 + tid;
            if (e < E) {
                int sn = ei[e], dn = ei[E + e];
                sSD[tid] = make_int2(sn, dn);
                float dx = pos[dn * 3 + 0] - pos[sn * 3 + 0];
                float dy = pos[dn * 3 + 1] - pos[sn * 3 + 1];
                float dz = pos[dn * 3 + 2] - pos[sn * 3 + 2];
                float dist = sqrtf(dx * dx + dy * dy + dz * dz + EPSF);
                float4 eav = *(const float4*)&ea[e * 4];
                sEIn[tid * 5 + 0] = dist;
                sEIn[tid * 5 + 1] = eav.x;
                sEIn[tid * 5 + 2] = eav.y;
                sEIn[tid * 5 + 3] = eav.z;
                sEIn[tid * 5 + 4] = eav.w;
                float inv = 1.f / dist;
                sU4[tid] = make_float4(dx * inv, dy * inv, dz * inv, 0.f);
            } else {
                sSD[tid] = make_int2(0, 0);
#pragma unroll
                for (int i = 0; i < 5; i++) sEIn[tid * 5 + i] = 0.f;
                sU4[tid] = make_float4(0.f, 0.f, 0.f, 0.f);
            }
        }
        __syncthreads();

        // GEMM1: h1T[c][e] = elu(b1[c] + edge_in[e] . W1[:,c])
        {
            int e = tid & (TILE - 1);
            int ch = tid >> 7;  // 0..1 -> 32 cols each; lanes in a warp share ch
            float ein[5];
#pragma unroll
            for (int i = 0; i < 5; i++) ein[i] = sEIn[e * 5 + i];
#pragma unroll
            for (int cc = 0; cc < 32; cc++) {
                int c = ch * 32 + cc;
                float a = sb1[c];
#pragma unroll
                for (int i = 0; i < 5; i++) a += ein[i] * sW1[i * H + c];
                h1T[c * TILE + e] = a > 0.f ? a : (__expf(a) - 1.f);
            }
        }
        __syncthreads();

        // GEMM2 (64 -> 96): 16 edges/warp as 8 f32x2 pairs per output group.
        unsigned long long aS[8], aV[8], aX[8];
        {
            unsigned long long bs, bv, bx;
            PACK2(bs, sb2[f]); PACK2(bv, sb2[F + f]); PACK2(bx, sb2[2 * F + f]);
#pragma unroll
            for (int p = 0; p < 8; p++) { aS[p] = bs; aV[p] = bv; aX[p] = bx; }
        }
#pragma unroll 2
        for (int k4 = 0; k4 < H / 4; k4++) {
            const float* wp = &sW2T[k4 * 384];
            float4 wsq = *(const float4*)&wp[f * 4];          // out = f,      k..k+3
            float4 wvq = *(const float4*)&wp[128 + f * 4];    // out = 32+f
            float4 wxq = *(const float4*)&wp[256 + f * 4];    // out = 64+f
            const float* wsA = &wsq.x; const float* wvA = &wvq.x; const float* wxA = &wxq.x;
#pragma unroll
            for (int kk = 0; kk < 4; kk++) {
                const float* hrow = &h1T[(k4 * 4 + kk) * TILE + eBase];
                ulonglong2 hA = *(const ulonglong2*)(hrow);
                ulonglong2 hB = *(const ulonglong2*)(hrow + 4);
                ulonglong2 hC = *(const ulonglong2*)(hrow + 8);
                ulonglong2 hD = *(const ulonglong2*)(hrow + 12);
                unsigned long long ws2, wv2, wx2;
                PACK2(ws2, wsA[kk]); PACK2(wv2, wvA[kk]); PACK2(wx2, wxA[kk]);
                FMA2(aS[0], hA.x, ws2); FMA2(aS[1], hA.y, ws2);
                FMA2(aS[2], hB.x, ws2); FMA2(aS[3], hB.y, ws2);
                FMA2(aS[4], hC.x, ws2); FMA2(aS[5], hC.y, ws2);
                FMA2(aS[6], hD.x, ws2); FMA2(aS[7], hD.y, ws2);
                FMA2(aV[0], hA.x, wv2); FMA2(aV[1], hA.y, wv2);
                FMA2(aV[2], hB.x, wv2); FMA2(aV[3], hB.y, wv2);
                FMA2(aV[4], hC.x, wv2); FMA2(aV[5], hC.y, wv2);
                FMA2(aV[6], hD.x, wv2); FMA2(aV[7], hD.y, wv2);
                FMA2(aX[0], hA.x, wx2); FMA2(aX[1], hA.y, wx2);
                FMA2(aX[2], hB.x, wx2); FMA2(aX[3], hB.y, wx2);
                FMA2(aX[4], hC.x, wx2); FMA2(aX[5], hC.y, wx2);
                FMA2(aX[6], hD.x, wx2); FMA2(aX[7], hD.y, wx2);
            }
        }

        // messages + scatter: per edge, lanes = f -> coalesced LDG.128 + RED.v4
#pragma unroll
        for (int p = 0; p < 8; p++) {
            unsigned int gsl, gsh, gvl, gvh, gxl, gxh;
            asm("mov.b64 {%0, %1}, %2;" : "=r"(gsl), "=r"(gsh) : "l"(aS[p]));
            asm("mov.b64 {%0, %1}, %2;" : "=r"(gvl), "=r"(gvh) : "l"(aV[p]));
            asm("mov.b64 {%0, %1}, %2;" : "=r"(gxl), "=r"(gxh) : "l"(aX[p]));
#pragma unroll
            for (int half = 0; half < 2; half++) {
                int e = eBase + p * 2 + half;
                if (e0 + e >= E) continue;
                float gs = __uint_as_float(half ? gsh : gsl);
                float gv = __uint_as_float(half ? gvh : gvl);
                float gx = __uint_as_float(half ? gxh : gxl);
                int2 sd = sSD[e];
                float4 u = sU4[e];
                float4 sv = d_sv[sd.x * F + f];   // coalesced across lanes
                float c = gx * sv.x;
                red_add_v4(&d_acc[sd.y * F + f],  // coalesced across lanes
                           gs * sv.x,
                           gv * sv.y + c * u.x,
                           gv * sv.z + c * u.y,
                           gv * sv.w + c * u.z);
            }
        }
    }
}

// ---------------- node update: s += elu(as@Ws); v += av@Wv ----------------
__global__ void __launch_bounds__(256) upd_kernel(const float* __restrict__ Ws,
                                                  const float* __restrict__ Wv, int Nn) {
    __shared__ float sWs[F * F], sWv[F * F];
    __shared__ float4 sA[8][F];
    int tid = threadIdx.x;
    for (int i = tid; i < F * F; i += 256) { sWs[i] = Ws[i]; sWv[i] = Wv[i]; }
    int ln = tid >> 5, f = tid & 31;
    int n = blockIdx.x * 8 + ln;
    bool ok = n < Nn;
    if (ok) {
        float inv = 1.f / fmaxf(d_cnt[n], 1.f);
        float4 a = d_acc[n * F + f];
        sA[ln][f] = make_float4(a.x * inv, a.y * inv, a.z * inv, a.w * inv);
        d_acc[n * F + f] = make_float4(0.f, 0.f, 0.f, 0.f);  // ready for next layer
    }
    __syncthreads();
    if (ok) {
        float a = 0, vx = 0, vy = 0, vz = 0;
#pragma unroll
        for (int g = 0; g < F; g++) {
            float w1 = sWs[g * F + f], w2 = sWv[g * F + f];
            float4 ag = sA[ln][g];
            a  += ag.x * w1;
            vx += ag.y * w2;
            vy += ag.z * w2;
            vz += ag.w * w2;
        }
        float4 cur = d_sv[n * F + f];
        cur.x += elu1(a);
        cur.y += vx;
        cur.z += vy;
        cur.w += vz;
        d_sv[n * F + f] = cur;
    }
}

// ---------------- graph node counts ----------------
__global__ void gcnt_kernel(const int* __restrict__ batch, int Nn) {
    int n = blockIdx.x * blockDim.x + threadIdx.x;
    if (n < Nn) atomicAdd(&d_gcnt[batch[n]], 1.f);
}

// ---------------- invariant map + graph-sum pooling ----------------
__global__ void __launch_bounds__(128) inv_kernel(const int* __restrict__ batch,
                                                  const float* __restrict__ Winv,
                                                  const float* __restrict__ binv, int Nn) {
    __shared__ float sW[2 * F * NINVC];  // 32KB
    __shared__ float sFeat[2 * F];
    int tid = threadIdx.x;
    for (int i = tid; i < 2 * F * NINVC; i += 128) sW[i] = Winv[i];
    float bj = binv[tid];
    int n0 = blockIdx.x * 32;
    for (int nn = 0; nn < 32; nn++) {
        int n = n0 + nn;
        if (n >= Nn) break;
        __syncthreads();
        if (tid < F) {
            float4 sv = d_sv[n * F + tid];
            sFeat[tid] = sv.x;
            sFeat[F + tid] = sqrtf(sv.y * sv.y + sv.z * sv.z + sv.w * sv.w + EPSF);
        }
        __syncthreads();
        float acc = bj;
#pragma unroll 8
        for (int i = 0; i < 2 * F; i++) acc += sFeat[i] * sW[i * NINVC + tid];
        atomicAdd(&d_xgsum[batch[n] * NINVC + tid], acc);
    }
}

// ---------------- mean pool finalize ----------------
__global__ void poolfin_kernel(int G) {
    int i = blockIdx.x * blockDim.x + threadIdx.x;
    if (i < G * NINVC) d_xg[i] = d_xgsum[i] / fmaxf(d_gcnt[i / NINVC], 1.f);
}

// ---------------- batchnorm column stats ----------------
__global__ void bnstats_kernel(int which, int G) {
    const float* z = which ? d_z1 : d_xg;
    float* mean = which ? d_m2 : d_m1;
    float* rstd = which ? d_r2 : d_r1;
    int j = blockIdx.x;
    __shared__ float sS[256], sQ[256];
    float s = 0.f, q = 0.f;
    for (int g = threadIdx.x; g < G; g += 256) {
        float val = z[g * NINVC + j];
        s += val; q += val * val;
    }
    sS[threadIdx.x] = s; sQ[threadIdx.x] = q;
    __syncthreads();
    for (int off = 128; off > 0; off >>= 1) {
        if (threadIdx.x < off) { sS[threadIdx.x] += sS[threadIdx.x + off]; sQ[threadIdx.x] += sQ[threadIdx.x + off]; }
        __syncthreads();
    }
    if (threadIdx.x == 0) {
        float m = sS[0] / (float)G;
        float var = sQ[0] / (float)G - m * m;
        mean[j] = m;
        rstd[j] = rsqrtf(var + 1e-5f);
    }
}

// ---------------- fc1 ----------------
__global__ void __launch_bounds__(128) fc1_kernel(const float* __restrict__ Wf1,
                                                  const float* __restrict__ bf1,
                                                  const float* __restrict__ g1,
                                                  const float* __restrict__ be1, int G) {
    __shared__ float sA[NINVC];
    int tid = threadIdx.x;
    float gj = g1[tid], bej = be1[tid], mj = d_m1[tid], rj = d_r1[tid], bfj = bf1[tid];
    int r0 = blockIdx.x * 16;
    for (int rr = 0; rr < 16; rr++) {
        int r = r0 + rr;
        if (r >= G) break;
        __syncthreads();
        float a = (d_xg[r * NINVC + tid] - mj) * rj * gj + bej;
        sA[tid] = elu1(a);
        __syncthreads();
        float acc = bfj;
#pragma unroll 8
        for (int i = 0; i < NINVC; i++) acc += sA[i] * Wf1[i * NINVC + tid];
        d_z1[r * NINVC + tid] = acc;
    }
}

// ---------------- fc2 ----------------
__global__ void fc2_kernel(const float* __restrict__ Wf2, const float* __restrict__ bf2,
                           const float* __restrict__ g2, const float* __restrict__ be2,
                           float* __restrict__ out, int G) {
    int warp = threadIdx.x >> 5, lane = threadIdx.x & 31;
    int r = blockIdx.x * 8 + warp;
    if (r >= G) return;
    float acc = 0.f;
    for (int j = lane; j < NINVC; j += 32) {
        float a = (d_z1[r * NINVC + j] - d_m2[j]) * d_r2[j] * g2[j] + be2[j];
        acc += elu1(a) * Wf2[j];
    }
#pragma unroll
    for (int off = 16; off > 0; off >>= 1) acc += __shfl_down_sync(0xffffffffu, acc, off);
    if (lane == 0) out[r] = acc + bf2[0];
}

// ---------------- launch ----------------
extern "C" void kernel_launch(void* const* d_in, const int* in_sizes, int n_in,
                              void* d_out, int out_size) {
    const float* x     = (const float*)d_in[0];
    const float* pos   = (const float*)d_in[1];
    const int*   ei    = (const int*)d_in[2];
    const float* ea    = (const float*)d_in[3];
    const int*   batch = (const int*)d_in[4];
    const float* Wes   = (const float*)d_in[5];
    const float* bes   = (const float*)d_in[6];
    const float* Wev   = (const float*)d_in[7];
    const float* W1    = (const float*)d_in[8];
    const float* b1    = (const float*)d_in[9];
    const float* W2    = (const float*)d_in[10];
    const float* b2    = (const float*)d_in[11];
    const float* Ws    = (const float*)d_in[12];
    const float* Wv    = (const float*)d_in[13];
    const float* Winv  = (const float*)d_in[14];
    const float* binv  = (const float*)d_in[15];
    const float* g1    = (const float*)d_in[16];
    const float* be1   = (const float*)d_in[17];
    const float* Wf1   = (const float*)d_in[18];
    const float* bf1   = (const float*)d_in[19];
    const float* g2    = (const float*)d_in[20];
    const float* be2   = (const float*)d_in[21];
    const float* Wf2   = (const float*)d_in[22];
    const float* bf2   = (const float*)d_in[23];

    int Nn = in_sizes[0] / 5;
    int E  = in_sizes[2] / 2;
    int G  = out_size;
    float* out = (float*)d_out;

    static int smem_set = 0;
    if (!smem_set) {
        cudaFuncSetAttribute(msg_kernel, cudaFuncAttributeMaxDynamicSharedMemorySize, SMEM_BYTES);
        smem_set = 1;
    }

    zero_kernel<<<2048, 256>>>();
    embed_kernel<<<(Nn * F + 255) / 256, 256>>>(x, pos, Wes, bes, Wev, Nn);
    degree_kernel<<<(E + 255) / 256, 256>>>(ei, E);

    for (int l = 0; l < 4; l++) {
        msg_kernel<<<888, 256, SMEM_BYTES>>>(pos, ei, ea,
                                             W1 + l * 5 * H, b1 + l * H,
                                             W2 + l * H * 3 * F, b2 + l * 3 * F, E);
        upd_kernel<<<(Nn + 7) / 8, 256>>>(Ws + l * F * F, Wv + l * F * F, Nn);
    }

    gcnt_kernel<<<(Nn + 255) / 256, 256>>>(batch, Nn);
    inv_kernel<<<(Nn + 31) / 32, 128>>>(batch, Winv, binv, Nn);
    poolfin_kernel<<<(G * NINVC + 255) / 256, 256>>>(G);
    bnstats_kernel<<<NINVC, 256>>>(0, G);
    fc1_kernel<<<(G + 15) / 16, 128>>>(Wf1, bf1, g1, be1, G);
    bnstats_kernel<<<NINVC, 256>>>(1, G);
    fc2_kernel<<<(G + 7) / 8, 256>>>(Wf2, bf2, g2, be2, out, G);
}

// round 10
// speedup vs baseline: 1.1701x; 1.1701x over previous
#include <cuda_runtime.h>
#include <math.h>

#define NN 50000
#define EE 800000
#define F 32
#define H 64
#define NINVC 128
#define GMAX 2048
#define EPSF 1e-6f
#define TILE 64

// ---------------- scratch (device globals; no allocation) ----------------
__device__ float4 d_sv[NN * F];    // packed node state {s, vx, vy, vz}
__device__ float4 d_acc[NN * F];   // packed accumulator {as, avx, avy, avz}
__device__ float d_cnt[NN];
__device__ float d_xgsum[GMAX * NINVC];
__device__ float d_gcnt[GMAX];
__device__ float d_xg[GMAX * NINVC];
__device__ float d_z1[GMAX * NINVC];
__device__ float d_m1[NINVC];
__device__ float d_r1[NINVC];
__device__ float d_m2[NINVC];
__device__ float d_r2[NINVC];

__device__ __forceinline__ float elu1(float x) { return x > 0.f ? x : expm1f(x); }

__device__ __forceinline__ void red_add_v4(float4* addr, float a, float b, float c, float d) {
    asm volatile("red.global.add.v4.f32 [%0], {%1, %2, %3, %4};"
                 :: "l"(addr), "f"(a), "f"(b), "f"(c), "f"(d) : "memory");
}

#define FMA2(acc, a, b) \
    asm("fma.rn.f32x2 %0, %1, %2, %0;" : "+l"(acc) : "l"(a), "l"(b))

#define PACK2(out, v) \
    asm("mov.b64 %0, {%1, %1};" : "=l"(out) : "r"(__float_as_uint(v)))

// ---------------- zero accumulators ----------------
__global__ void zero_kernel() {
    int stride = gridDim.x * blockDim.x;
    float4 z4 = make_float4(0.f, 0.f, 0.f, 0.f);
    for (int i = blockIdx.x * blockDim.x + threadIdx.x; i < NN * F; i += stride) {
        d_acc[i] = z4;
        if (i < NN) d_cnt[i] = 0.f;
        if (i < GMAX * NINVC) d_xgsum[i] = 0.f;
        if (i < GMAX) d_gcnt[i] = 0.f;
    }
}

// ---------------- embedding ----------------
__global__ void embed_kernel(const float* __restrict__ x, const float* __restrict__ pos,
                             const float* __restrict__ Wes, const float* __restrict__ bes,
                             const float* __restrict__ Wev, int Nn) {
    int idx = blockIdx.x * blockDim.x + threadIdx.x;
    if (idx >= Nn * F) return;
    int n = idx / F, f = idx & (F - 1);
    float xs[5];
#pragma unroll
    for (int i = 0; i < 5; i++) xs[i] = x[n * 5 + i];
    float as = bes[f], av = 0.f;
#pragma unroll
    for (int i = 0; i < 5; i++) { as += xs[i] * Wes[i * F + f]; av += xs[i] * Wev[i * F + f]; }
    float px = pos[n * 3], py = pos[n * 3 + 1], pz = pos[n * 3 + 2];
    d_sv[idx] = make_float4(as, av * px, av * py, av * pz);
}

// ---------------- in-degree over dst ----------------
__global__ void degree_kernel(const int* __restrict__ ei, int E) {
    int e = blockIdx.x * blockDim.x + threadIdx.x;
    if (e < E) atomicAdd(&d_cnt[ei[E + e]], 1.f);
}

// ---------------- fused edge MLP + message + scatter (per layer) ----------------
// Round-6 structure: 64-edge tile, warp owns 8 edges, lane = feature f.
// New: W2 paired over k (float2 loads), packed edge metadata, pinned occupancy.
__global__ void __launch_bounds__(256, 4) msg_kernel(
    const float* __restrict__ pos, const int* __restrict__ ei,
    const float* __restrict__ ea,
    const float* __restrict__ W1, const float* __restrict__ b1,
    const float* __restrict__ W2, const float* __restrict__ b2, int E) {
    __shared__ float sW1[5 * H];        // 320
    __shared__ float sb1[H];            // 64
    __shared__ float sW2P[H * 96];      // 6144 : [k/2][col][2] paired over k
    __shared__ float sb2[3 * F];        // 96
    __shared__ float sEIn[TILE * 5];    // 320
    __shared__ float4 sU4[TILE];        // 256
    __shared__ int2 sSD[TILE];          // 128
    __shared__ float h1T[H * TILE];     // 4096 : [k][e]

    int tid = threadIdx.x;
    for (int i = tid; i < 5 * H; i += 256) sW1[i] = W1[i];
    if (tid < H) sb1[tid] = b1[tid];
    if (tid < 96) sb2[tid] = b2[tid];
    // paired layout: sW2P[k2*192 + col*2 + kk] = W2[(k2*2+kk)*96 + col]
    for (int i = tid; i < H * 96; i += 256) {
        int k2 = i / 192, r = i % 192, col = r >> 1, kk = r & 1;
        sW2P[i] = W2[(k2 * 2 + kk) * 96 + col];
    }

    int w = tid >> 5;       // warp 0..7
    int f = tid & 31;       // lane = feature
    int eBase = w * 8;      // warp owns 8 edges

    int ntiles = (E + TILE - 1) / TILE;
    for (int t = blockIdx.x; t < ntiles; t += gridDim.x) {
        int e0 = t * TILE;
        __syncthreads();  // previous tile consumed; weights visible
        if (tid < TILE) {
            int e = e0 + tid;
            if (e < E) {
                int sn = ei[e], dn = ei[E + e];
                sSD[tid] = make_int2(sn, dn);
                float dx = pos[dn * 3 + 0] - pos[sn * 3 + 0];
                float dy = pos[dn * 3 + 1] - pos[sn * 3 + 1];
                float dz = pos[dn * 3 + 2] - pos[sn * 3 + 2];
                float dist = sqrtf(dx * dx + dy * dy + dz * dz + EPSF);
                float4 eav = *(const float4*)&ea[e * 4];
                sEIn[tid * 5 + 0] = dist;
                sEIn[tid * 5 + 1] = eav.x;
                sEIn[tid * 5 + 2] = eav.y;
                sEIn[tid * 5 + 3] = eav.z;
                sEIn[tid * 5 + 4] = eav.w;
                float inv = 1.f / dist;
                sU4[tid] = make_float4(dx * inv, dy * inv, dz * inv, 0.f);
            } else {
                sSD[tid] = make_int2(0, 0);
#pragma unroll
                for (int i = 0; i < 5; i++) sEIn[tid * 5 + i] = 0.f;
                sU4[tid] = make_float4(0.f, 0.f, 0.f, 0.f);
            }
        }
        __syncthreads();

        // GEMM1: h1T[c][e] = elu(b1[c] + edge_in[e] . W1[:,c])
        {
            int e = tid & (TILE - 1);
            int ch = tid >> 6;  // 0..3 -> 16 cols each
            float ein[5];
#pragma unroll
            for (int i = 0; i < 5; i++) ein[i] = sEIn[e * 5 + i];
#pragma unroll
            for (int cc = 0; cc < 16; cc++) {
                int c = ch * 16 + cc;
                float a = sb1[c];
#pragma unroll
                for (int i = 0; i < 5; i++) a += ein[i] * sW1[i * H + c];
                h1T[c * TILE + e] = a > 0.f ? a : (__expf(a) - 1.f);
            }
        }
        __syncthreads();

        // GEMM2 (64 -> 96): 8 edges/warp as 4 f32x2 pairs; k processed 2 at a time.
        unsigned long long aS[4], aV[4], aX[4];
        {
            unsigned long long bs, bv, bx;
            PACK2(bs, sb2[f]); PACK2(bv, sb2[F + f]); PACK2(bx, sb2[2 * F + f]);
#pragma unroll
            for (int p = 0; p < 4; p++) { aS[p] = bs; aV[p] = bv; aX[p] = bx; }
        }
#pragma unroll 4
        for (int k2 = 0; k2 < H / 2; k2++) {
            const float* wp = &sW2P[k2 * 192];
            float2 wsp = *(const float2*)&wp[f * 2];              // out=f,    k,k+1
            float2 wvp = *(const float2*)&wp[(F + f) * 2];        // out=32+f
            float2 wxp = *(const float2*)&wp[(2 * F + f) * 2];    // out=64+f
#pragma unroll
            for (int kk = 0; kk < 2; kk++) {
                const float* hrow = &h1T[(k2 * 2 + kk) * TILE + eBase];
                ulonglong2 hA = *(const ulonglong2*)(hrow);       // edges 0-3
                ulonglong2 hB = *(const ulonglong2*)(hrow + 4);   // edges 4-7
                unsigned long long ws2, wv2, wx2;
                PACK2(ws2, kk ? wsp.y : wsp.x);
                PACK2(wv2, kk ? wvp.y : wvp.x);
                PACK2(wx2, kk ? wxp.y : wxp.x);
                FMA2(aS[0], hA.x, ws2); FMA2(aS[1], hA.y, ws2);
                FMA2(aS[2], hB.x, ws2); FMA2(aS[3], hB.y, ws2);
                FMA2(aV[0], hA.x, wv2); FMA2(aV[1], hA.y, wv2);
                FMA2(aV[2], hB.x, wv2); FMA2(aV[3], hB.y, wv2);
                FMA2(aX[0], hA.x, wx2); FMA2(aX[1], hA.y, wx2);
                FMA2(aX[2], hB.x, wx2); FMA2(aX[3], hB.y, wx2);
            }
        }

        // messages + scatter: per edge, lanes = f -> coalesced LDG.128 + RED.v4
#pragma unroll
        for (int p = 0; p < 4; p++) {
            unsigned int gsl, gsh, gvl, gvh, gxl, gxh;
            asm("mov.b64 {%0, %1}, %2;" : "=r"(gsl), "=r"(gsh) : "l"(aS[p]));
            asm("mov.b64 {%0, %1}, %2;" : "=r"(gvl), "=r"(gvh) : "l"(aV[p]));
            asm("mov.b64 {%0, %1}, %2;" : "=r"(gxl), "=r"(gxh) : "l"(aX[p]));
#pragma unroll
            for (int half = 0; half < 2; half++) {
                int e = eBase + p * 2 + half;
                if (e0 + e >= E) continue;
                float gs = __uint_as_float(half ? gsh : gsl);
                float gv = __uint_as_float(half ? gvh : gvl);
                float gx = __uint_as_float(half ? gxh : gxl);
                int2 sd = sSD[e];
                float4 u = sU4[e];
                float4 sv = d_sv[sd.x * F + f];   // coalesced across lanes
                float c = gx * sv.x;
                red_add_v4(&d_acc[sd.y * F + f],  // coalesced across lanes
                           gs * sv.x,
                           gv * sv.y + c * u.x,
                           gv * sv.z + c * u.y,
                           gv * sv.w + c * u.z);
            }
        }
    }
}

// ---------------- node update: s += elu(as@Ws); v += av@Wv ----------------
__global__ void __launch_bounds__(256) upd_kernel(const float* __restrict__ Ws,
                                                  const float* __restrict__ Wv, int Nn) {
    __shared__ float sWs[F * F], sWv[F * F];
    __shared__ float4 sA[8][F];
    int tid = threadIdx.x;
    for (int i = tid; i < F * F; i += 256) { sWs[i] = Ws[i]; sWv[i] = Wv[i]; }
    int ln = tid >> 5, f = tid & 31;
    int n = blockIdx.x * 8 + ln;
    bool ok = n < Nn;
    if (ok) {
        float inv = 1.f / fmaxf(d_cnt[n], 1.f);
        float4 a = d_acc[n * F + f];
        sA[ln][f] = make_float4(a.x * inv, a.y * inv, a.z * inv, a.w * inv);
        d_acc[n * F + f] = make_float4(0.f, 0.f, 0.f, 0.f);  // ready for next layer
    }
    __syncthreads();
    if (ok) {
        float a = 0, vx = 0, vy = 0, vz = 0;
#pragma unroll
        for (int g = 0; g < F; g++) {
            float w1 = sWs[g * F + f], w2 = sWv[g * F + f];
            float4 ag = sA[ln][g];
            a  += ag.x * w1;
            vx += ag.y * w2;
            vy += ag.z * w2;
            vz += ag.w * w2;
        }
        float4 cur = d_sv[n * F + f];
        cur.x += elu1(a);
        cur.y += vx;
        cur.z += vy;
        cur.w += vz;
        d_sv[n * F + f] = cur;
    }
}

// ---------------- graph node counts ----------------
__global__ void gcnt_kernel(const int* __restrict__ batch, int Nn) {
    int n = blockIdx.x * blockDim.x + threadIdx.x;
    if (n < Nn) atomicAdd(&d_gcnt[batch[n]], 1.f);
}

// ---------------- invariant map + graph-sum pooling ----------------
__global__ void __launch_bounds__(128) inv_kernel(const int* __restrict__ batch,
                                                  const float* __restrict__ Winv,
                                                  const float* __restrict__ binv, int Nn) {
    __shared__ float sW[2 * F * NINVC];  // 32KB
    __shared__ float sFeat[2 * F];
    int tid = threadIdx.x;
    for (int i = tid; i < 2 * F * NINVC; i += 128) sW[i] = Winv[i];
    float bj = binv[tid];
    int n0 = blockIdx.x * 32;
    for (int nn = 0; nn < 32; nn++) {
        int n = n0 + nn;
        if (n >= Nn) break;
        __syncthreads();
        if (tid < F) {
            float4 sv = d_sv[n * F + tid];
            sFeat[tid] = sv.x;
            sFeat[F + tid] = sqrtf(sv.y * sv.y + sv.z * sv.z + sv.w * sv.w + EPSF);
        }
        __syncthreads();
        float acc = bj;
#pragma unroll 8
        for (int i = 0; i < 2 * F; i++) acc += sFeat[i] * sW[i * NINVC + tid];
        atomicAdd(&d_xgsum[batch[n] * NINVC + tid], acc);
    }
}

// ---------------- mean pool finalize ----------------
__global__ void poolfin_kernel(int G) {
    int i = blockIdx.x * blockDim.x + threadIdx.x;
    if (i < G * NINVC) d_xg[i] = d_xgsum[i] / fmaxf(d_gcnt[i / NINVC], 1.f);
}

// ---------------- batchnorm column stats ----------------
__global__ void bnstats_kernel(int which, int G) {
    const float* z = which ? d_z1 : d_xg;
    float* mean = which ? d_m2 : d_m1;
    float* rstd = which ? d_r2 : d_r1;
    int j = blockIdx.x;
    __shared__ float sS[256], sQ[256];
    float s = 0.f, q = 0.f;
    for (int g = threadIdx.x; g < G; g += 256) {
        float val = z[g * NINVC + j];
        s += val; q += val * val;
    }
    sS[threadIdx.x] = s; sQ[threadIdx.x] = q;
    __syncthreads();
    for (int off = 128; off > 0; off >>= 1) {
        if (threadIdx.x < off) { sS[threadIdx.x] += sS[threadIdx.x + off]; sQ[threadIdx.x] += sQ[threadIdx.x + off]; }
        __syncthreads();
    }
    if (threadIdx.x == 0) {
        float m = sS[0] / (float)G;
        float var = sQ[0] / (float)G - m * m;
        mean[j] = m;
        rstd[j] = rsqrtf(var + 1e-5f);
    }
}

// ---------------- fc1 ----------------
__global__ void __launch_bounds__(128) fc1_kernel(const float* __restrict__ Wf1,
                                                  const float* __restrict__ bf1,
                                                  const float* __restrict__ g1,
                                                  const float* __restrict__ be1, int G) {
    __shared__ float sA[NINVC];
    int tid = threadIdx.x;
    float gj = g1[tid], bej = be1[tid], mj = d_m1[tid], rj = d_r1[tid], bfj = bf1[tid];
    int r0 = blockIdx.x * 16;
    for (int rr = 0; rr < 16; rr++) {
        int r = r0 + rr;
        if (r >= G) break;
        __syncthreads();
        float a = (d_xg[r * NINVC + tid] - mj) * rj * gj + bej;
        sA[tid] = elu1(a);
        __syncthreads();
        float acc = bfj;
#pragma unroll 8
        for (int i = 0; i < NINVC; i++) acc += sA[i] * Wf1[i * NINVC + tid];
        d_z1[r * NINVC + tid] = acc;
    }
}

// ---------------- fc2 ----------------
__global__ void fc2_kernel(const float* __restrict__ Wf2, const float* __restrict__ bf2,
                           const float* __restrict__ g2, const float* __restrict__ be2,
                           float* __restrict__ out, int G) {
    int warp = threadIdx.x >> 5, lane = threadIdx.x & 31;
    int r = blockIdx.x * 8 + warp;
    if (r >= G) return;
    float acc = 0.f;
    for (int j = lane; j < NINVC; j += 32) {
        float a = (d_z1[r * NINVC + j] - d_m2[j]) * d_r2[j] * g2[j] + be2[j];
        acc += elu1(a) * Wf2[j];
    }
#pragma unroll
    for (int off = 16; off > 0; off >>= 1) acc += __shfl_down_sync(0xffffffffu, acc, off);
    if (lane == 0) out[r] = acc + bf2[0];
}

// ---------------- launch ----------------
extern "C" void kernel_launch(void* const* d_in, const int* in_sizes, int n_in,
                              void* d_out, int out_size) {
    const float* x     = (const float*)d_in[0];
    const float* pos   = (const float*)d_in[1];
    const int*   ei    = (const int*)d_in[2];
    const float* ea    = (const float*)d_in[3];
    const int*   batch = (const int*)d_in[4];
    const float* Wes   = (const float*)d_in[5];
    const float* bes   = (const float*)d_in[6];
    const float* Wev   = (const float*)d_in[7];
    const float* W1    = (const float*)d_in[8];
    const float* b1    = (const float*)d_in[9];
    const float* W2    = (const float*)d_in[10];
    const float* b2    = (const float*)d_in[11];
    const float* Ws    = (const float*)d_in[12];
    const float* Wv    = (const float*)d_in[13];
    const float* Winv  = (const float*)d_in[14];
    const float* binv  = (const float*)d_in[15];
    const float* g1    = (const float*)d_in[16];
    const float* be1   = (const float*)d_in[17];
    const float* Wf1   = (const float*)d_in[18];
    const float* bf1   = (const float*)d_in[19];
    const float* g2    = (const float*)d_in[20];
    const float* be2   = (const float*)d_in[21];
    const float* Wf2   = (const float*)d_in[22];
    const float* bf2   = (const float*)d_in[23];

    int Nn = in_sizes[0] / 5;
    int E  = in_sizes[2] / 2;
    int G  = out_size;
    float* out = (float*)d_out;

    zero_kernel<<<2048, 256>>>();
    embed_kernel<<<(Nn * F + 255) / 256, 256>>>(x, pos, Wes, bes, Wev, Nn);
    degree_kernel<<<(E + 255) / 256, 256>>>(ei, E);

    for (int l = 0; l < 4; l++) {
        msg_kernel<<<1480, 256>>>(pos, ei, ea,
                                  W1 + l * 5 * H, b1 + l * H,
                                  W2 + l * H * 3 * F, b2 + l * 3 * F, E);
        upd_kernel<<<(Nn + 7) / 8, 256>>>(Ws + l * F * F, Wv + l * F * F, Nn);
    }

    gcnt_kernel<<<(Nn + 255) / 256, 256>>>(batch, Nn);
    inv_kernel<<<(Nn + 31) / 32, 128>>>(batch, Winv, binv, Nn);
    poolfin_kernel<<<(G * NINVC + 255) / 256, 256>>>(G);
    bnstats_kernel<<<NINVC, 256>>>(0, G);
    fc1_kernel<<<(G + 15) / 16, 128>>>(Wf1, bf1, g1, be1, G);
    bnstats_kernel<<<NINVC, 256>>>(1, G);
    fc2_kernel<<<(G + 7) / 8, 256>>>(Wf2, bf2, g2, be2, out, G);
}